// round 5
// baseline (speedup 1.0000x reference)
#include <cuda_runtime.h>
#include <cuda_bf16.h>
#include <math.h>

// ---------------------------------------------------------------------------
// PCENetwork: patch-conditional experts, 2 layers + pool + classifier
// B=16, H=W=208
// Layer0: ps=16 (13x13=169 patches), Cin=3, E=8, Cout=8, then 1x1 fc 8->8
// Layer1: ps=13 (16x16=256 patches), Cin=8, E=8, Cout=16, then 1x1 fc 16->16
// Pool: 26x26 mean; fc1+pool fused into layer1 via per-patch channel sums
// Classifier: [16,1024] @ [100,1024]^T + b
// f32x2 packed FMA over oc pairs; activations stored PRE-DUPLICATED (v,v)
// in shared so the FFMA2 broadcast operand is a single LDS.64 (no MOVs).
// ---------------------------------------------------------------------------

#define BATCH 16
#define HW 208

typedef unsigned long long u64;

__device__ float g_x1[BATCH * 8 * HW * HW];      // layer0 output (after fc0)
__device__ float g_scores0[169 * 8];
__device__ float g_scores1[256 * 8];
__device__ float g_A0[8 * 20];
__device__ float g_c0[8];
__device__ float g_A1[8 * 20];
__device__ float g_c1[8];
__device__ float g_pooled[BATCH * 16 * 8 * 8];   // [b][c][8][8]

// ---- f32x2 helpers --------------------------------------------------------
__device__ __forceinline__ u64 f2_pack(float lo, float hi) {
    u64 out; unsigned a = __float_as_uint(lo), b = __float_as_uint(hi);
    asm("mov.b64 %0, {%1, %2};" : "=l"(out) : "r"(a), "r"(b));
    return out;
}
__device__ __forceinline__ u64 f2_fma(u64 a, u64 b, u64 c) {
    u64 d;
    asm("fma.rn.f32x2 %0, %1, %2, %3;" : "=l"(d) : "l"(a), "l"(b), "l"(c));
    return d;
}
__device__ __forceinline__ void f2_unpack(u64 v, float& lo, float& hi) {
    unsigned a, b;
    asm("mov.b64 {%0, %1}, %2;" : "=r"(a), "=r"(b) : "l"(v));
    lo = __uint_as_float(a); hi = __uint_as_float(b);
}

// ---------------------------------------------------------------------------
// Launch 1: router prep (collapse proj/keys into A(8x20), c(8)) + zero pooled
// ---------------------------------------------------------------------------
__global__ void prep_zero_kernel(const float* __restrict__ pw0, const float* __restrict__ pb0,
                                 const float* __restrict__ k0,
                                 const float* __restrict__ pw1, const float* __restrict__ pb1,
                                 const float* __restrict__ k1) {
    int tid = threadIdx.x;
    if (tid < 160) {
        int e = tid / 20, c = tid % 20;
        float v = 0.f;
        for (int d = 0; d < 128; d++) v += k0[e * 128 + d] * pw0[d * 20 + c];
        g_A0[tid] = v;
    } else if (tid < 168) {
        int e = tid - 160;
        float v = 0.f;
        for (int d = 0; d < 128; d++) v += k0[e * 128 + d] * pb0[d];
        g_c0[e] = v;
    } else if (tid < 328) {
        int t = tid - 168;
        int e = t / 20, c = t % 20;
        float v = 0.f;
        for (int d = 0; d < 128; d++) v += k1[e * 128 + d] * pw1[d * 20 + c];
        g_A1[t] = v;
    } else if (tid < 336) {
        int e = tid - 328;
        float v = 0.f;
        for (int d = 0; d < 128; d++) v += k1[e * 128 + d] * pb1[d];
        g_c1[e] = v;
    }
    for (int i = tid; i < BATCH * 16 * 64; i += 512) g_pooled[i] = 0.f;
}

// ---------------------------------------------------------------------------
// Launch 2: BOTH routers in one grid (blocks 0..168 = layer0, 169..424 = L1)
// ---------------------------------------------------------------------------
__global__ void routers_kernel() {
    int pa = blockIdx.x;
    int ps, gw, p;
    const float *A, *cb;
    float* scores;
    if (pa < 169) { ps = 16; gw = 13; p = pa;       A = g_A0; cb = g_c0; scores = g_scores0; }
    else          { ps = 13; gw = 16; p = pa - 169; A = g_A1; cb = g_c1; scores = g_scores1; }

    int ph = p / gw, pw = p % gw;
    __shared__ float s_phi[20];
    int tid = threadIdx.x;
    if (tid < 20) s_phi[tid] = 0.f;
    __syncthreads();

    float loc[20];
#pragma unroll
    for (int i = 0; i < 20; i++) loc[i] = 0.f;

    const float PI = 3.14159265358979323846f;
    int n = ps * ps;
    for (int i = tid; i < n; i += blockDim.x) {
        int y = i / ps, x = i % ps;
        int gy = ph * ps + y, gx = pw * ps + x;
        float yy = (2.0f * (float)gy) / 207.0f - 1.0f;
        float xx = (2.0f * (float)gx) / 207.0f - 1.0f;
        float r = sqrtf(xx * xx + yy * yy);
        float a = atan2f(yy, xx);
        loc[0] += xx; loc[1] += yy; loc[2] += r; loc[3] += a;
        float base[4] = {xx, yy, r, a};
        int c = 4;
#pragma unroll
        for (int f = 1; f <= 2; f++) {
            float w = (f == 1 ? 2.0f : 4.0f) * PI;
#pragma unroll
            for (int bb = 0; bb < 4; bb++) {
                float sv, cv;
                sincosf(w * base[bb], &sv, &cv);
                loc[c++] += sv;
                loc[c++] += cv;
            }
        }
    }
#pragma unroll
    for (int k = 0; k < 20; k++) {
        float v = loc[k];
#pragma unroll
        for (int off = 16; off; off >>= 1) v += __shfl_down_sync(0xffffffffu, v, off);
        if ((tid & 31) == 0) atomicAdd(&s_phi[k], v);
    }
    __syncthreads();
    if (tid == 0) {
        float inv = 1.0f / (float)n;
        float logit[8];
        float mx = -1e30f;
#pragma unroll
        for (int e = 0; e < 8; e++) {
            float v = cb[e];
            for (int c = 0; c < 20; c++) v += A[e * 20 + c] * (s_phi[c] * inv);
            logit[e] = v;
            mx = fmaxf(mx, v);
        }
        float sum = 0.f;
#pragma unroll
        for (int e = 0; e < 8; e++) { logit[e] = expf(logit[e] - mx); sum += logit[e]; }
        float s2 = 0.f;
#pragma unroll
        for (int e = 0; e < 8; e++) {
            float sc = logit[e] / sum;
            sc = (sc > 0.0625f) ? sc : 0.f;
            logit[e] = sc;
            s2 += sc;
        }
        float inv2 = 1.0f / (s2 + 1e-6f);
#pragma unroll
        for (int e = 0; e < 8; e++) scores[p * 8 + e] = logit[e] * inv2;
    }
}

// ---------------------------------------------------------------------------
// Launch 3 — Layer 0 (f32x2): block per (b,patch); 64 threads =
// (ocPair 0..3, row 0..15). Tile stored duplicated (v,v) -> LDS.64 broadcast.
// fc0 fused via smem staging.
// ---------------------------------------------------------------------------
__global__ __launch_bounds__(64) void layer0_kernel(
        const float* __restrict__ X, const float* __restrict__ w_exp,
        const float* __restrict__ b_exp, const float* __restrict__ w_fc,
        const float* __restrict__ b_fc) {
    int bp = blockIdx.x;
    int b = bp / 169, p = bp % 169;
    int ph = p / 13, pw = p % 13;

    __shared__ float2 s_w2[8 * 4 * 3 * 9];   // [e][ocq][ic][9] paired oc
    __shared__ float2 s_b2[8 * 4];
    __shared__ float2 s_tile2[3 * 18 * 18];  // duplicated (v,v), 7.8 KB
    __shared__ float s_comb[8][16][16];      // fc0 staging
    __shared__ float s_fc[64], s_bfc[8], s_sc[8];

    int tid = threadIdx.x;
    for (int i = tid; i < 864; i += 64) {
        int k = i % 9, t = i / 9;
        int ic = t % 3; t /= 3;
        int ocq = t & 3, e = t >> 2;
        int base = ((e * 8 + 2 * ocq) * 3 + ic) * 9 + k;
        s_w2[i] = make_float2(w_exp[base], w_exp[base + 27]);
    }
    if (tid < 32) {
        int e = tid >> 2, ocq = tid & 3;
        s_b2[tid] = make_float2(b_exp[e * 8 + 2 * ocq], b_exp[e * 8 + 2 * ocq + 1]);
    }
    if (tid < 64) s_fc[tid] = w_fc[tid];
    if (tid < 8) { s_bfc[tid] = b_fc[tid]; s_sc[tid] = g_scores0[p * 8 + tid]; }
    for (int i = tid; i < 3 * 18 * 18; i += 64) s_tile2[i] = make_float2(0.f, 0.f);
    __syncthreads();

    int y0 = ph * 16, x0 = pw * 16;
    for (int i = tid; i < 3 * 256; i += 64) {
        int c = i >> 8, r = i & 255;
        int y = r >> 4, x = r & 15;
        float v = X[((b * 3 + c) * HW + y0 + y) * HW + x0 + x];
        s_tile2[(c * 18 + y + 1) * 18 + x + 1] = make_float2(v, v);
    }
    __syncthreads();

    int row = tid & 15;      // output row within patch
    int ocq = tid >> 4;      // 0..3 -> oc = 2*ocq, 2*ocq+1

    float comb0[16], comb1[16];
#pragma unroll
    for (int px = 0; px < 16; px++) { comb0[px] = 0.f; comb1[px] = 0.f; }

    for (int e = 0; e < 8; e++) {
        float s = s_sc[e];
        if (s == 0.f) continue;
        u64 acc[16];
        {
            float2 bb = s_b2[e * 4 + ocq];
            u64 bp2 = f2_pack(bb.x, bb.y);
#pragma unroll
            for (int px = 0; px < 16; px++) acc[px] = bp2;
        }
#pragma unroll
        for (int ic = 0; ic < 3; ic++) {
            const u64* wp = (const u64*)&s_w2[((e * 4 + ocq) * 3 + ic) * 9];
#pragma unroll
            for (int ky = 0; ky < 3; ky++) {
                u64 w0 = wp[ky * 3 + 0], w1 = wp[ky * 3 + 1], w2 = wp[ky * 3 + 2];
                const u64* tr = (const u64*)&s_tile2[(ic * 18 + row + ky) * 18];
                u64 tb[18];
#pragma unroll
                for (int j = 0; j < 18; j++) tb[j] = tr[j];
#pragma unroll
                for (int px = 0; px < 16; px++) {
                    u64 v = acc[px];
                    v = f2_fma(w0, tb[px], v);
                    v = f2_fma(w1, tb[px + 1], v);
                    v = f2_fma(w2, tb[px + 2], v);
                    acc[px] = v;
                }
            }
        }
#pragma unroll
        for (int px = 0; px < 16; px++) {
            float lo, hi;
            f2_unpack(acc[px], lo, hi);
            comb0[px] += s * fmaxf(lo, 0.f);
            comb1[px] += s * fmaxf(hi, 0.f);
        }
    }

#pragma unroll
    for (int px = 0; px < 16; px++) {
        s_comb[2 * ocq + 0][row][px] = comb0[px];
        s_comb[2 * ocq + 1][row][px] = comb1[px];
    }
    __syncthreads();

    // fc0 (1x1, 8->8): thread handles 4 consecutive pixels -> float4 stores
    {
        int i0 = tid * 4;
        int y = i0 >> 4, xb = i0 & 15;
        float cv[8][4];
#pragma unroll
        for (int k = 0; k < 8; k++)
#pragma unroll
            for (int j = 0; j < 4; j++) cv[k][j] = s_comb[k][y][xb + j];
        int gy = y0 + y, gx = x0 + xb;
#pragma unroll
        for (int c = 0; c < 8; c++) {
            float4 out;
            float* po = (float*)&out;
#pragma unroll
            for (int j = 0; j < 4; j++) {
                float v = s_bfc[c];
#pragma unroll
                for (int k = 0; k < 8; k++) v += s_fc[c * 8 + k] * cv[k][j];
                po[j] = v;
            }
            *(float4*)&g_x1[((size_t)(b * 8 + c) * HW + gy) * HW + gx] = out;
        }
    }
}

// ---------------------------------------------------------------------------
// Launch 4 — Layer 1 (f32x2) + fc1 + pool. Block per (b, patch); 128 threads,
// 104 active = (ocPair 0..7, row 0..12). Tile stored duplicated (v,v).
// Per-patch channel sums -> fc1 -> atomicAdd into g_pooled.
// Dynamic smem: weights (4608 float2) + tile (1800 float2) = 51,264 B.
// ---------------------------------------------------------------------------
__global__ __launch_bounds__(128) void layer1_kernel(
        const float* __restrict__ w_exp, const float* __restrict__ b_exp,
        const float* __restrict__ w_fc, const float* __restrict__ b_fc) {
    extern __shared__ float2 dyn2[];
    float2* s_w2 = dyn2;                     // [e][ocq][ic][9] paired oc
    float2* s_tile2 = dyn2 + 4608;           // [ic][15][15] duplicated (v,v)

    __shared__ float2 s_b2[8 * 8];
    __shared__ float s_fc[256], s_bfc[16], s_sc[8], s_S[16];

    int bp = blockIdx.x;
    int b = bp >> 8, p = bp & 255;
    int ph = p >> 4, pw = p & 15;

    int tid = threadIdx.x;
    for (int i = tid; i < 4608; i += 128) {
        int k = i % 9, t = i / 9;
        int ic = t & 7; t >>= 3;
        int ocq = t & 7, e = t >> 3;
        int base = ((e * 16 + 2 * ocq) * 8 + ic) * 9 + k;
        s_w2[i] = make_float2(w_exp[base], w_exp[base + 72]);
    }
    if (tid < 64) {
        int e = tid >> 3, ocq = tid & 7;
        s_b2[tid] = make_float2(b_exp[e * 16 + 2 * ocq], b_exp[e * 16 + 2 * ocq + 1]);
    }
    for (int i = tid; i < 256; i += 128) s_fc[i] = w_fc[i];
    if (tid < 16) { s_bfc[tid] = b_fc[tid]; s_S[tid] = 0.f; }
    if (tid < 8) s_sc[tid] = g_scores1[p * 8 + tid];
    for (int i = tid; i < 8 * 15 * 15; i += 128) s_tile2[i] = make_float2(0.f, 0.f);
    __syncthreads();

    for (int i = tid; i < 8 * 169; i += 128) {
        int c = i / 169, rr = i % 169;
        int y = rr / 13, x = rr % 13;
        float v = g_x1[((size_t)(b * 8 + c) * HW + ph * 13 + y) * HW + pw * 13 + x];
        s_tile2[(c * 15 + y + 1) * 15 + x + 1] = make_float2(v, v);
    }
    __syncthreads();

    if (tid < 104) {
        int ocq = tid / 13;    // 0..7 -> oc = 2*ocq, 2*ocq+1
        int row = tid % 13;

        float sum0 = 0.f, sum1 = 0.f;
        for (int e = 0; e < 8; e++) {
            float s = s_sc[e];
            if (s == 0.f) continue;
            u64 acc[13];
            {
                float2 bb = s_b2[e * 8 + ocq];
                u64 bp2 = f2_pack(bb.x, bb.y);
#pragma unroll
                for (int px = 0; px < 13; px++) acc[px] = bp2;
            }
#pragma unroll
            for (int ic = 0; ic < 8; ic++) {
                const u64* wp = (const u64*)&s_w2[((e * 8 + ocq) * 8 + ic) * 9];
#pragma unroll
                for (int ky = 0; ky < 3; ky++) {
                    u64 w0 = wp[ky * 3 + 0], w1 = wp[ky * 3 + 1], w2 = wp[ky * 3 + 2];
                    const u64* tr = (const u64*)&s_tile2[(ic * 15 + row + ky) * 15];
                    u64 tb[15];
#pragma unroll
                    for (int j = 0; j < 15; j++) tb[j] = tr[j];
#pragma unroll
                    for (int px = 0; px < 13; px++) {
                        u64 v = acc[px];
                        v = f2_fma(w0, tb[px], v);
                        v = f2_fma(w1, tb[px + 1], v);
                        v = f2_fma(w2, tb[px + 2], v);
                        acc[px] = v;
                    }
                }
            }
            float rs0 = 0.f, rs1 = 0.f;
#pragma unroll
            for (int px = 0; px < 13; px++) {
                float lo, hi;
                f2_unpack(acc[px], lo, hi);
                rs0 += fmaxf(lo, 0.f);
                rs1 += fmaxf(hi, 0.f);
            }
            sum0 += s * rs0;
            sum1 += s * rs1;
        }
        atomicAdd(&s_S[2 * ocq + 0], sum0);
        atomicAdd(&s_S[2 * ocq + 1], sum1);
    }
    __syncthreads();

    // fc1 on patch channel sums, accumulate into pool cell (ph/2, pw/2)
    if (tid < 16) {
        int c = tid;
        float v = 169.0f * s_bfc[c];
#pragma unroll
        for (int k = 0; k < 16; k++) v += s_fc[c * 16 + k] * s_S[k];
        atomicAdd(&g_pooled[((b * 16 + c) * 8 + (ph >> 1)) * 8 + (pw >> 1)],
                  v * (1.0f / 676.0f));
    }
}

// ---------------------------------------------------------------------------
// Launch 5 — Classifier: [16,1024] @ w_cls[100,1024]^T + b_cls -> [16,100]
// ---------------------------------------------------------------------------
__global__ void cls_kernel(const float* __restrict__ w, const float* __restrict__ bias,
                           float* __restrict__ out) {
    int b = blockIdx.x;
    __shared__ float s_p[1024];
    for (int i = threadIdx.x; i < 1024; i += blockDim.x) s_p[i] = g_pooled[b * 1024 + i];
    __syncthreads();
    for (int j = threadIdx.x; j < 100; j += blockDim.x) {
        float v = bias[j];
        const float* wr = &w[j * 1024];
        for (int k = 0; k < 1024; k++) v += wr[k] * s_p[k];
        out[b * 100 + j] = v;
    }
}

// ---------------------------------------------------------------------------
extern "C" void kernel_launch(void* const* d_in, const int* in_sizes, int n_in,
                              void* d_out, int out_size) {
    const float* X       = (const float*)d_in[0];
    const float* w_exp0  = (const float*)d_in[1];
    const float* b_exp0  = (const float*)d_in[2];
    const float* w_fc0   = (const float*)d_in[3];
    const float* b_fc0   = (const float*)d_in[4];
    const float* proj_w0 = (const float*)d_in[5];
    const float* proj_b0 = (const float*)d_in[6];
    const float* keys0   = (const float*)d_in[7];
    const float* w_exp1  = (const float*)d_in[8];
    const float* b_exp1  = (const float*)d_in[9];
    const float* w_fc1   = (const float*)d_in[10];
    const float* b_fc1   = (const float*)d_in[11];
    const float* proj_w1 = (const float*)d_in[12];
    const float* proj_b1 = (const float*)d_in[13];
    const float* keys1   = (const float*)d_in[14];
    const float* w_cls   = (const float*)d_in[15];
    const float* b_cls   = (const float*)d_in[16];
    float* out = (float*)d_out;

    const int DYN1 = (4608 + 1800) * sizeof(float2);   // 51,264 bytes
    static int configured = 0;
    if (!configured) {
        cudaFuncSetAttribute(layer1_kernel, cudaFuncAttributeMaxDynamicSharedMemorySize, DYN1);
        configured = 1;
    }

    prep_zero_kernel<<<1, 512>>>(proj_w0, proj_b0, keys0, proj_w1, proj_b1, keys1);
    routers_kernel<<<425, 256>>>();
    layer0_kernel<<<BATCH * 169, 64>>>(X, w_exp0, b_exp0, w_fc0, b_fc0);
    layer1_kernel<<<BATCH * 256, 128, DYN1>>>(w_exp1, b_exp1, w_fc1, b_fc1);
    cls_kernel<<<BATCH, 128>>>(w_cls, b_cls, out);
}